// round 10
// baseline (speedup 1.0000x reference)
#include <cuda_runtime.h>
#include <math.h>

#define MAX_NODES 50000
#define E_MAX     800000
#define IN_DIM 100
#define HID 16
#define NC 40
#define GRID 296          // 2 blocks per SM on 148 SMs -> all co-resident
#define BS   512

// Scratch (no allocations allowed). Zero-initialized at load; every call
// restores g_deg to zero. Barrier gen counter is monotonic (no reset needed).
__device__ float g_Y  [MAX_NODES * HID];
__device__ float g_Z1 [MAX_NODES * HID];
__device__ float g_Z2 [MAX_NODES * HID];
__device__ int   g_deg [MAX_NODES];        // invariant: 0 at call entry/exit
__device__ int   g_off [MAX_NODES + 1];
__device__ int   g_pos [MAX_NODES];
__device__ int   g_bsum[GRID];
__device__ int2  g_csr [E_MAX];            // (src, bitcast(val)) sorted by dst
__device__ int          g_barcnt;          // resets itself each barrier
__device__ volatile int g_bargen;          // monotonic across calls/replays

// Grid-wide barrier. Safe: all GRID blocks are co-resident (launch_bounds
// guarantees 2 blocks/SM; GRID = 2*148).
__device__ __forceinline__ void gsync() {
    __threadfence();
    __syncthreads();
    if (threadIdx.x == 0) {
        int gen = g_bargen;
        if (atomicAdd(&g_barcnt, 1) == GRID - 1) {
            g_barcnt = 0;
            __threadfence();
            g_bargen = gen + 1;
        } else {
            while (g_bargen == gen) { }
        }
        __threadfence();
    }
    __syncthreads();
}

// Warp-per-node CSR gather row: 16 dims x 2 slots, 16 edges per iteration,
// 8-wide MLP (batch edge-record loads, then independent gathers).
template <bool RELU>
__device__ __forceinline__ float gather_row(const float* __restrict__ X,
                                            int beg, int end, int j, int h) {
    float acc = 0.f;
    for (int e0 = beg; e0 < end; e0 += 16) {
        int2 c[8];
#pragma unroll
        for (int k = 0; k < 8; k++) {
            int idx = e0 + 2 * k + h;
            c[k] = (idx < end) ? __ldg(&g_csr[idx]) : make_int2(0, 0); // val=0
        }
        float x[8];
#pragma unroll
        for (int k = 0; k < 8; k++)
            x[k] = __ldg(X + (size_t)c[k].x * HID + j);
#pragma unroll
        for (int k = 0; k < 8; k++) {
            float xv = RELU ? fmaxf(x[k], 0.f) : x[k];
            acc += __int_as_float(c[k].y) * xv;
        }
    }
    return acc;
}

__global__ void __launch_bounds__(BS, 2)
mega_kernel(const float* __restrict__ X,
            const int*   __restrict__ esrc,
            const int*   __restrict__ edst,
            const float* __restrict__ evals,
            const float* __restrict__ W1,
            const float* __restrict__ W2,
            float* __restrict__ out, int N, int E) {
    __shared__ float4 sW1[IN_DIM * 4];     // sW1[k*4+j4] = W1[k][4j4..]
    __shared__ float4 sW2[HID * (NC / 4)]; // sW2[k*10+c4] = W2[k][4c4..]
    __shared__ int wsum[16];
    __shared__ int s_pref;

    const int tid = threadIdx.x;
    const int gtid = blockIdx.x * BS + tid;
    const int gthreads = GRID * BS;

    for (int i = tid; i < IN_DIM * 4; i += BS) sW1[i] = ((const float4*)W1)[i];
    for (int i = tid; i < HID * (NC / 4); i += BS) sW2[i] = ((const float4*)W2)[i];
    __syncthreads();

    // ============ PHASE A: gemm1 (Y = X@W1) + degree histogram ============
    for (int n = gtid; n < N; n += gthreads) {
        const float4* xr = (const float4*)(X + (size_t)n * IN_DIM);
        float acc[HID];
#pragma unroll
        for (int j = 0; j < HID; j++) acc[j] = 0.f;
#pragma unroll 5
        for (int k4 = 0; k4 < IN_DIM / 4; k4++) {
            float4 f = __ldg(xr + k4);
            float fk[4] = {f.x, f.y, f.z, f.w};
#pragma unroll
            for (int kk = 0; kk < 4; kk++) {
                int k = k4 * 4 + kk;
#pragma unroll
                for (int j4 = 0; j4 < 4; j4++) {
                    float4 wv = sW1[k * 4 + j4];
                    acc[j4*4+0] += fk[kk] * wv.x;
                    acc[j4*4+1] += fk[kk] * wv.y;
                    acc[j4*4+2] += fk[kk] * wv.z;
                    acc[j4*4+3] += fk[kk] * wv.w;
                }
            }
        }
        float4* yo = (float4*)(g_Y + (size_t)n * HID);
#pragma unroll
        for (int j4 = 0; j4 < 4; j4++)
            yo[j4] = make_float4(acc[j4*4+0], acc[j4*4+1], acc[j4*4+2], acc[j4*4+3]);
    }
    {
        int E4 = (E + 3) / 4;
        for (int t = gtid; t < E4; t += gthreads) {
            int base = t * 4;
            if (base + 3 < E) {
                int4 d = __ldg((const int4*)edst + t);
                atomicAdd(&g_deg[d.x], 1); atomicAdd(&g_deg[d.y], 1);
                atomicAdd(&g_deg[d.z], 1); atomicAdd(&g_deg[d.w], 1);
            } else {
                for (int e = base; e < E; e++) atomicAdd(&g_deg[edst[e]], 1);
            }
        }
    }
    gsync();

    // ============ PHASE B: exclusive scan of g_deg -> g_off/g_pos ============
    // B1: block-local scan of this block's contiguous chunk; publish total.
    const int C = (N + GRID - 1) / GRID;           // 169
    const int cbase = blockIdx.x * C;
    int cnt = N - cbase; if (cnt > C) cnt = C; if (cnt < 0) cnt = 0;
    int v = (tid < cnt) ? g_deg[cbase + tid] : 0;
    int lane = tid & 31, wid = tid >> 5;
    int x = v;
#pragma unroll
    for (int off = 1; off < 32; off <<= 1) {
        int y = __shfl_up_sync(0xffffffffu, x, off);
        if (lane >= off) x += y;
    }
    if (lane == 31) wsum[wid] = x;
    __syncthreads();
    if (wid == 0) {
        int wv = (lane < 16) ? wsum[lane] : 0;
#pragma unroll
        for (int off = 1; off < 16; off <<= 1) {
            int y = __shfl_up_sync(0xffffffffu, wv, off);
            if (lane >= off) wv += y;
        }
        if (lane < 16) wsum[lane] = wv;
    }
    __syncthreads();
    int incl = x + (wid ? wsum[wid - 1] : 0);
    if (tid == 0) g_bsum[blockIdx.x] = wsum[15];
    gsync();

    // B2: add prefix of preceding block totals; finalize + zero g_deg.
    if (tid == 0) s_pref = 0;
    __syncthreads();
    if (tid < (int)blockIdx.x) atomicAdd_block(&s_pref, g_bsum[tid]);
    __syncthreads();
    {
        int excl = s_pref + incl - v;
        int i = cbase + tid;
        if (tid < cnt) { g_off[i] = excl; g_pos[i] = excl; g_deg[i] = 0; }
        if (blockIdx.x == 0 && tid == 0) g_off[N] = E;
    }
    gsync();

    // ============ PHASE C: scatter edges into dst-sorted CSR ============
    {
        int E4 = (E + 3) / 4;
        for (int t = gtid; t < E4; t += gthreads) {
            int base = t * 4;
            if (base + 3 < E) {
                int4   s = __ldg((const int4*)esrc + t);
                int4   d = __ldg((const int4*)edst + t);
                float4 w = __ldg((const float4*)evals + t);
                g_csr[atomicAdd(&g_pos[d.x], 1)] = make_int2(s.x, __float_as_int(w.x));
                g_csr[atomicAdd(&g_pos[d.y], 1)] = make_int2(s.y, __float_as_int(w.y));
                g_csr[atomicAdd(&g_pos[d.z], 1)] = make_int2(s.z, __float_as_int(w.z));
                g_csr[atomicAdd(&g_pos[d.w], 1)] = make_int2(s.w, __float_as_int(w.w));
            } else {
                for (int e = base; e < E; e++)
                    g_csr[atomicAdd(&g_pos[edst[e]], 1)] =
                        make_int2(esrc[e], __float_as_int(evals[e]));
            }
        }
    }
    gsync();

    // ============ PHASE D/E: two gather SpMMs (warp per node) ============
    {
        const int gwarp = gtid >> 5, nwarps = gthreads >> 5;
        const int j = lane & 15, h = lane >> 4;
        for (int n = gwarp; n < N; n += nwarps) {
            int beg = __ldg(&g_off[n]), end = __ldg(&g_off[n + 1]);
            float acc = gather_row<false>(g_Y, beg, end, j, h);
            acc += __shfl_xor_sync(0xffffffffu, acc, 16);
            if (lane < 16) g_Z1[(size_t)n * HID + lane] = acc;
        }
        gsync();
        for (int n = gwarp; n < N; n += nwarps) {
            int beg = __ldg(&g_off[n]), end = __ldg(&g_off[n + 1]);
            float acc = gather_row<true>(g_Z1, beg, end, j, h);
            acc += __shfl_xor_sync(0xffffffffu, acc, 16);
            if (lane < 16) g_Z2[(size_t)n * HID + lane] = acc;
        }
    }
    gsync();

    // ============ PHASE F: out = log_softmax(Z2 @ W2), 2 threads/node ======
    // Pair (even,odd) threads handle classes [0..20) / [20..40); combine the
    // max and exp-sum with one shfl_xor each. All lanes participate in
    // shuffles (inactive lanes compute on a clamped node, stores predicated).
    for (int p = gtid; p < 2 * ((N + 1) & ~1); p += gthreads) {
        int n = p >> 1;
        int half = p & 1;
        bool live = (n < N);
        int nc = live ? n : N - 1;
        const float4* zp = (const float4*)(g_Z2 + (size_t)nc * HID);
        float4 zv0 = __ldg(zp), zv1 = __ldg(zp+1), zv2 = __ldg(zp+2), zv3 = __ldg(zp+3);
        float z[HID] = {zv0.x, zv0.y, zv0.z, zv0.w, zv1.x, zv1.y, zv1.z, zv1.w,
                        zv2.x, zv2.y, zv2.z, zv2.w, zv3.x, zv3.y, zv3.z, zv3.w};
        float acc[NC / 2];
#pragma unroll
        for (int c = 0; c < NC / 2; c++) acc[c] = 0.f;
#pragma unroll
        for (int k = 0; k < HID; k++) {
#pragma unroll
            for (int c4 = 0; c4 < 5; c4++) {
                float4 wv = sW2[k * (NC / 4) + half * 5 + c4];
                acc[c4*4+0] += z[k] * wv.x;
                acc[c4*4+1] += z[k] * wv.y;
                acc[c4*4+2] += z[k] * wv.z;
                acc[c4*4+3] += z[k] * wv.w;
            }
        }
        float m = acc[0];
#pragma unroll
        for (int c = 1; c < NC / 2; c++) m = fmaxf(m, acc[c]);
        m = fmaxf(m, __shfl_xor_sync(0xffffffffu, m, 1));
        float s = 0.f;
#pragma unroll
        for (int c = 0; c < NC / 2; c++) s += __expf(acc[c] - m);
        s += __shfl_xor_sync(0xffffffffu, s, 1);
        float lse = m + __logf(s);
        if (live) {
            float4* o = (float4*)(out + (size_t)n * NC + half * (NC / 2));
#pragma unroll
            for (int c4 = 0; c4 < 5; c4++)
                o[c4] = make_float4(acc[c4*4+0]-lse, acc[c4*4+1]-lse,
                                    acc[c4*4+2]-lse, acc[c4*4+3]-lse);
        }
    }
}

// ---------------------------------------------------------------------------
extern "C" void kernel_launch(void* const* d_in, const int* in_sizes, int n_in,
                              void* d_out, int out_size) {
    const float* features = (const float*)d_in[0];
    const int*   esrc     = (const int*)  d_in[1];
    const int*   edst     = (const int*)  d_in[2];
    const float* evals    = (const float*)d_in[3];
    const float* W1       = (const float*)d_in[4];
    const float* W2       = (const float*)d_in[5];
    float*       out      = (float*)d_out;

    int N = in_sizes[0] / IN_DIM;   // 50000
    int E = in_sizes[1];            // 800000

    mega_kernel<<<GRID, BS>>>(features, esrc, edst, evals, W1, W2, out, N, E);
}

// round 11
// speedup vs baseline: 1.6881x; 1.6881x over previous
#include <cuda_runtime.h>
#include <math.h>

#define MAX_NODES 50000
#define E_MAX     800000
#define IN_DIM 100
#define HID 16
#define NC 40
#define SCAN_BS 1024
#define NB_MAX ((MAX_NODES + SCAN_BS - 1) / SCAN_BS)   // 49

// Scratch (no allocations allowed). All zero at process start; every call
// restores g_deg and g_bpub to zero, so each graph replay sees identical state.
__device__ float g_Y  [MAX_NODES * HID];   // X @ W1
__device__ float g_Z1 [MAX_NODES * HID];   // A @ Y
__device__ float g_Z2 [MAX_NODES * HID];   // A @ relu(Z1)
__device__ int   g_deg [MAX_NODES];        // invariant: 0 at call entry/exit
__device__ int   g_off [MAX_NODES + 1];
__device__ int   g_pos [MAX_NODES];
__device__ volatile int g_bpub[NB_MAX];    // scan publish: total+1, 0=not ready
__device__ int2  g_csr [E_MAX];            // (src, bitcast(val)) sorted by dst

// ---------------------------------------------------------------------------
// K1: fused  [blocks 0..Gg)  : gemm1  Y = X @ W1  (one thread per node)
//            [blocks Gg..end): hist   g_deg[dst]++ (4 edges/thread, RED)
// ---------------------------------------------------------------------------
__global__ void k1_gemm_hist(const float* __restrict__ X,
                             const float* __restrict__ W1,
                             const int* __restrict__ dst,
                             int N, int E, int Gg) {
    if ((int)blockIdx.x >= Gg) {          // ---- histogram role ----
        int t = (blockIdx.x - Gg) * blockDim.x + threadIdx.x;
        int base = t * 4;
        if (base + 3 < E) {
            int4 d = __ldg((const int4*)dst + t);
            atomicAdd(&g_deg[d.x], 1); atomicAdd(&g_deg[d.y], 1);
            atomicAdd(&g_deg[d.z], 1); atomicAdd(&g_deg[d.w], 1);
        } else {
            for (int e = base; e < E; e++) atomicAdd(&g_deg[dst[e]], 1);
        }
        return;
    }
    // ---- gemm1 role ----
    __shared__ float4 w[IN_DIM * 4];                  // w[k*4+j4] = W1[k][4j4..]
    for (int i = threadIdx.x; i < IN_DIM * 4; i += blockDim.x)
        w[i] = ((const float4*)W1)[i];
    __syncthreads();
    int n = blockIdx.x * blockDim.x + threadIdx.x;
    if (n >= N) return;

    const float4* xr = (const float4*)(X + (size_t)n * IN_DIM);
    float acc[HID];
#pragma unroll
    for (int j = 0; j < HID; j++) acc[j] = 0.f;
#pragma unroll 5
    for (int k4 = 0; k4 < IN_DIM / 4; k4++) {
        float4 f = __ldg(xr + k4);
        float fk[4] = {f.x, f.y, f.z, f.w};
#pragma unroll
        for (int kk = 0; kk < 4; kk++) {
            int k = k4 * 4 + kk;
#pragma unroll
            for (int j4 = 0; j4 < 4; j4++) {
                float4 wv = w[k * 4 + j4];
                acc[j4*4+0] += fk[kk] * wv.x;
                acc[j4*4+1] += fk[kk] * wv.y;
                acc[j4*4+2] += fk[kk] * wv.z;
                acc[j4*4+3] += fk[kk] * wv.w;
            }
        }
    }
    float4* yo = (float4*)(g_Y + (size_t)n * HID);
#pragma unroll
    for (int j4 = 0; j4 < 4; j4++)
        yo[j4] = make_float4(acc[j4*4+0], acc[j4*4+1], acc[j4*4+2], acc[j4*4+3]);
}

// ---------------------------------------------------------------------------
// K2: single-kernel exclusive scan of g_deg -> g_off/g_pos (49 co-resident
// blocks, full lookback via one-word volatile publish). Zeroes g_deg.
// ---------------------------------------------------------------------------
__global__ void k2_scan(int N, int E) {
    int tid = threadIdx.x, b = blockIdx.x;
    int i = b * SCAN_BS + tid;
    int v = (i < N) ? g_deg[i] : 0;

    int lane = tid & 31, wid = tid >> 5;
    int x = v;
#pragma unroll
    for (int off = 1; off < 32; off <<= 1) {
        int y = __shfl_up_sync(0xffffffffu, x, off);
        if (lane >= off) x += y;
    }
    __shared__ int wsum[32];
    if (lane == 31) wsum[wid] = x;
    __syncthreads();
    if (wid == 0) {
        int wv = wsum[lane];
#pragma unroll
        for (int off = 1; off < 32; off <<= 1) {
            int y = __shfl_up_sync(0xffffffffu, wv, off);
            if (lane >= off) wv += y;
        }
        wsum[lane] = wv;
    }
    __syncthreads();
    int incl = x + (wid ? wsum[wid - 1] : 0);
    int total = wsum[31];

    if (tid == 0) g_bpub[b] = total + 1;   // publish (total+1, 0 = pending)

    __shared__ int pref;
    if (tid == 0) pref = 0;
    __syncthreads();
    if (tid < b) {
        int p;
        while ((p = g_bpub[tid]) == 0) { }
        atomicAdd(&pref, p - 1);
    }
    __syncthreads();

    int excl = pref + incl - v;
    if (i < N) { g_off[i] = excl; g_pos[i] = excl; g_deg[i] = 0; }
    if (b == 0 && tid == 0) g_off[N] = E;
}

// ---------------------------------------------------------------------------
// K3: scatter edges into dst-sorted CSR; resets scan publish flags.
// ---------------------------------------------------------------------------
__global__ void k3_scatter(const int* __restrict__ src,
                           const int* __restrict__ dst,
                           const float* __restrict__ val, int E) {
    if (blockIdx.x == 0 && threadIdx.x < NB_MAX) g_bpub[threadIdx.x] = 0;
    int t = blockIdx.x * blockDim.x + threadIdx.x;
    int base = t * 4;
    if (base + 3 < E) {
        int4   s = __ldg((const int4*)src + t);
        int4   d = __ldg((const int4*)dst + t);
        float4 v = __ldg((const float4*)val + t);
        g_csr[atomicAdd(&g_pos[d.x], 1)] = make_int2(s.x, __float_as_int(v.x));
        g_csr[atomicAdd(&g_pos[d.y], 1)] = make_int2(s.y, __float_as_int(v.y));
        g_csr[atomicAdd(&g_pos[d.z], 1)] = make_int2(s.z, __float_as_int(v.z));
        g_csr[atomicAdd(&g_pos[d.w], 1)] = make_int2(s.w, __float_as_int(v.w));
    } else {
        for (int e = base; e < E; e++)
            g_csr[atomicAdd(&g_pos[dst[e]], 1)] = make_int2(src[e], __float_as_int(val[e]));
    }
}

// ---------------------------------------------------------------------------
// K4/K5: gather SpMM, warp per node, lanes = 16 dims x 2 edge slots.
// MLP-8: batch 8 predicated edge-record loads, then 8 INDEPENDENT row
// gathers, then FMAs. Avg degree 16 -> one batched iteration per node
// (~2 serialized L2 round-trips instead of ~16).
// ---------------------------------------------------------------------------
template <bool RELU>
__device__ __forceinline__ float gather_row(const float* __restrict__ X,
                                            int beg, int end, int j, int h) {
    float acc = 0.f;
    for (int e0 = beg; e0 < end; e0 += 16) {
        int2 c[8];
#pragma unroll
        for (int k = 0; k < 8; k++) {
            int idx = e0 + 2 * k + h;
            c[k] = (idx < end) ? __ldg(&g_csr[idx]) : make_int2(0, 0); // val=0
        }
        float x[8];
#pragma unroll
        for (int k = 0; k < 8; k++)
            x[k] = __ldg(X + (size_t)c[k].x * HID + j);   // 64B coalesced each
#pragma unroll
        for (int k = 0; k < 8; k++) {
            float xv = RELU ? fmaxf(x[k], 0.f) : x[k];
            acc += __int_as_float(c[k].y) * xv;
        }
    }
    return acc;
}

template <bool FIRST>
__global__ void spmm_gather_kernel(int N) {
    int t = blockIdx.x * blockDim.x + threadIdx.x;
    int n = t >> 5;
    if (n >= N) return;
    int lane = t & 31, j = lane & 15, h = lane >> 4;
    const float* __restrict__ X = FIRST ? g_Y : g_Z1;
    float*       __restrict__ Z = FIRST ? g_Z1 : g_Z2;
    int beg = __ldg(&g_off[n]), end = __ldg(&g_off[n + 1]);
    float acc = gather_row<!FIRST>(X, beg, end, j, h);
    acc += __shfl_xor_sync(0xffffffffu, acc, 16);
    if (lane < 16) Z[(size_t)n * HID + lane] = acc;
}

// ---------------------------------------------------------------------------
// K6: out[n] = log_softmax( Z2[n, 0:16] @ W2[16, 40] ), one thread per node.
// ---------------------------------------------------------------------------
__global__ void out_kernel(const float* __restrict__ W2,
                           float* __restrict__ out, int N) {
    __shared__ float4 w4[HID * (NC / 4)];
    for (int i = threadIdx.x; i < HID * (NC / 4); i += blockDim.x)
        w4[i] = ((const float4*)W2)[i];
    __syncthreads();
    int n = blockIdx.x * blockDim.x + threadIdx.x;
    if (n >= N) return;

    const float4* zp = (const float4*)(g_Z2 + (size_t)n * HID);
    float4 zv[4] = {__ldg(zp), __ldg(zp+1), __ldg(zp+2), __ldg(zp+3)};
    float z[HID] = {zv[0].x, zv[0].y, zv[0].z, zv[0].w,
                    zv[1].x, zv[1].y, zv[1].z, zv[1].w,
                    zv[2].x, zv[2].y, zv[2].z, zv[2].w,
                    zv[3].x, zv[3].y, zv[3].z, zv[3].w};
    float acc[NC];
#pragma unroll
    for (int c = 0; c < NC; c++) acc[c] = 0.f;
#pragma unroll
    for (int k = 0; k < HID; k++) {
#pragma unroll
        for (int c4 = 0; c4 < NC / 4; c4++) {
            float4 wv = w4[k * (NC / 4) + c4];
            acc[c4*4+0] += z[k] * wv.x;
            acc[c4*4+1] += z[k] * wv.y;
            acc[c4*4+2] += z[k] * wv.z;
            acc[c4*4+3] += z[k] * wv.w;
        }
    }
    float m = acc[0];
#pragma unroll
    for (int c = 1; c < NC; c++) m = fmaxf(m, acc[c]);
    float s = 0.f;
#pragma unroll
    for (int c = 0; c < NC; c++) s += __expf(acc[c] - m);
    float lse = m + __logf(s);
    float4* o = (float4*)(out + (size_t)n * NC);
#pragma unroll
    for (int c4 = 0; c4 < NC / 4; c4++)
        o[c4] = make_float4(acc[c4*4+0]-lse, acc[c4*4+1]-lse,
                            acc[c4*4+2]-lse, acc[c4*4+3]-lse);
}

// ---------------------------------------------------------------------------
extern "C" void kernel_launch(void* const* d_in, const int* in_sizes, int n_in,
                              void* d_out, int out_size) {
    const float* features = (const float*)d_in[0];
    const int*   esrc     = (const int*)  d_in[1];
    const int*   edst     = (const int*)  d_in[2];
    const float* evals    = (const float*)d_in[3];
    const float* W1       = (const float*)d_in[4];
    const float* W2       = (const float*)d_in[5];
    float*       out      = (float*)d_out;

    int N = in_sizes[0] / IN_DIM;   // 50000
    int E = in_sizes[1];            // 800000
    int NB = (N + SCAN_BS - 1) / SCAN_BS;   // 49
    int E4 = (E + 3) / 4;

    int Gg = (N + 127) / 128;               // gemm1 blocks
    int Gh = (E4 + 127) / 128;              // hist blocks

    k1_gemm_hist<<<Gg + Gh, 128>>>(features, W1, edst, N, E, Gg);
    k2_scan     <<<NB, SCAN_BS>>>(N, E);
    k3_scatter  <<<(E4 + 255) / 256, 256>>>(esrc, edst, evals, E);
    spmm_gather_kernel<true ><<<((long)N * 32 + 255) / 256, 256>>>(N);
    spmm_gather_kernel<false><<<((long)N * 32 + 255) / 256, 256>>>(N);
    out_kernel  <<<(N + 127) / 128, 128>>>(W2, out, N);
}